// round 6
// baseline (speedup 1.0000x reference)
#include <cuda_runtime.h>
#include <math.h>

#define BB   2
#define LL   1024
#define DD   1024
#define HH   16
#define DH   64
#define DFF_ 4096
#define NL_  2
#define MR   (BB*LL)   // 2048 rows

// ---------------- scratch (no allocation allowed) ----------------
__device__ float g_h[MR*DD];
__device__ float g_q[MR*DD];
__device__ float g_k[MR*DD];
__device__ float g_v[MR*DD];
__device__ float g_a[MR*DD];
__device__ float g_f[MR*DFF_];

// ---------------- rmsnorm: one block per row (D=1024, 256 thr x float4) ----------------
__global__ void rmsnorm_kernel(const float* __restrict__ x,
                               const float* __restrict__ w,
                               float* __restrict__ o) {
    int row = blockIdx.x;
    int t = threadIdx.x;
    const float4* xr = (const float4*)(x + (size_t)row * DD);
    float4 v = xr[t];
    float ss = v.x*v.x + v.y*v.y + v.z*v.z + v.w*v.w;
    #pragma unroll
    for (int off = 16; off; off >>= 1) ss += __shfl_xor_sync(0xFFFFFFFFu, ss, off);
    __shared__ float wsum[8];
    __shared__ float inv_s;
    if ((t & 31) == 0) wsum[t >> 5] = ss;
    __syncthreads();
    if (t == 0) {
        float tot = 0.f;
        #pragma unroll
        for (int i = 0; i < 8; i++) tot += wsum[i];
        inv_s = rsqrtf(tot * (1.0f / DD) + 1e-5f);
    }
    __syncthreads();
    float inv = inv_s;
    const float4* wr = (const float4*)w;
    float4 wv = wr[t];
    float4 r;
    r.x = v.x * inv * wv.x;
    r.y = v.y * inv * wv.y;
    r.z = v.z * inv * wv.z;
    r.w = v.w * inv * wv.w;
    ((float4*)(o + (size_t)row * DD))[t] = r;
}

// ---------------- tiled SGEMM: C[M,N] = A[M,K] * B[N,K]^T ----------------
// BM=BN=128, BK=8, 256 threads, 8x8 per-thread tile.
// EPI: 0 = plain store, 1 = residual add (+ optional bias), 2 = exact GELU
template<int EPI>
__global__ void __launch_bounds__(256) gemm_nt(const float* __restrict__ A,
                                               const float* __restrict__ B,
                                               float* __restrict__ C,
                                               const float* __restrict__ bias,
                                               int K) {
    __shared__ __align__(16) float As[8][128];
    __shared__ __align__(16) float Bs[8][128];
    int t  = threadIdx.x;
    int lr = t >> 1;            // 0..127 load row
    int lc = (t & 1) << 2;      // 0 or 4 (float4 k-offset)
    const float* Ap = A + ((size_t)((blockIdx.y << 7) + lr)) * K + lc;
    const float* Bp = B + ((size_t)((blockIdx.x << 7) + lr)) * K + lc;

    int tr = (t >> 4) << 3;     // row within tile, 0..120
    int tc = (t & 15) << 3;     // col within tile, 0..120

    float acc[8][8];
    #pragma unroll
    for (int i = 0; i < 8; i++)
        #pragma unroll
        for (int j = 0; j < 8; j++) acc[i][j] = 0.f;

    for (int kk = 0; kk < K; kk += 8) {
        float4 a4 = *(const float4*)(Ap + kk);
        float4 b4 = *(const float4*)(Bp + kk);
        As[lc+0][lr] = a4.x; As[lc+1][lr] = a4.y; As[lc+2][lr] = a4.z; As[lc+3][lr] = a4.w;
        Bs[lc+0][lr] = b4.x; Bs[lc+1][lr] = b4.y; Bs[lc+2][lr] = b4.z; Bs[lc+3][lr] = b4.w;
        __syncthreads();
        #pragma unroll
        for (int k = 0; k < 8; k++) {
            float ra[8], rb[8];
            *(float4*)&ra[0] = *(const float4*)&As[k][tr];
            *(float4*)&ra[4] = *(const float4*)&As[k][tr + 4];
            *(float4*)&rb[0] = *(const float4*)&Bs[k][tc];
            *(float4*)&rb[4] = *(const float4*)&Bs[k][tc + 4];
            #pragma unroll
            for (int i = 0; i < 8; i++)
                #pragma unroll
                for (int j = 0; j < 8; j++)
                    acc[i][j] = fmaf(ra[i], rb[j], acc[i][j]);
        }
        __syncthreads();
    }

    int N    = gridDim.x << 7;
    int row0 = (blockIdx.y << 7) + tr;
    int col0 = (blockIdx.x << 7) + tc;
    #pragma unroll
    for (int i = 0; i < 8; i++) {
        float* cp = C + (size_t)(row0 + i) * N + col0;
        #pragma unroll
        for (int j = 0; j < 8; j++) {
            float v = acc[i][j];
            if (EPI == 2) {
                v = 0.5f * v * (1.0f + erff(v * 0.7071067811865476f));
            } else if (EPI == 1) {
                v += cp[j];
                if (bias) v += bias[col0 + j];
            }
            cp[j] = v;
        }
    }
}

// ---------------- causal linear attention scan ----------------
// One block per (b, h). 256 threads: te = t&63 (e index), dg = t>>6 (d group of 16).
// State S[d][e]: thread holds 16 values (d = dg*16+j).
__global__ void linattn_kernel(const float* __restrict__ Q,
                               const float* __restrict__ K,
                               const float* __restrict__ V,
                               float* __restrict__ A) {
    int bh = blockIdx.x;
    int b  = bh / HH;
    int h  = bh % HH;
    int t  = threadIdx.x;
    int e  = t & 63;
    int dg = t >> 6;

    __shared__ float sK[64], sV[64], sQ[64];
    __shared__ float sP[4][64];

    float s[16];
    #pragma unroll
    for (int j = 0; j < 16; j++) s[j] = 0.f;

    size_t base = (size_t)b * LL * DD + (size_t)h * DH;
    for (int l = 0; l < LL; l++) {
        size_t off = base + (size_t)l * DD;
        if (t < 64)        sK[t]       = K[off + t];
        else if (t < 128)  sV[t - 64]  = V[off + (t - 64)];
        else if (t < 192)  sQ[t - 128] = Q[off + (t - 128)];
        __syncthreads();
        float ve = sV[e];
        float p  = 0.f;
        #pragma unroll
        for (int j = 0; j < 16; j++) {
            int d = dg * 16 + j;
            s[j] = fmaf(sK[d], ve, s[j]);
            p    = fmaf(sQ[d], s[j], p);
        }
        sP[dg][e] = p;
        __syncthreads();
        if (t < 64)
            A[off + t] = sP[0][t] + sP[1][t] + sP[2][t] + sP[3][t];
    }
}

// ---------------- host launcher ----------------
extern "C" void kernel_launch(void* const* d_in, const int* in_sizes, int n_in,
                              void* d_out, int out_size) {
    const float* x_in  = (const float*)d_in[0];
    const float* qw    = (const float*)d_in[1];
    const float* kw    = (const float*)d_in[2];
    const float* vw    = (const float*)d_in[3];
    const float* ow    = (const float*)d_in[4];
    const float* pn_w  = (const float*)d_in[5];
    const float* ln_w  = (const float*)d_in[6];
    const float* fc_w  = (const float*)d_in[7];
    const float* fc2_w = (const float*)d_in[8];
    const float* fc2_b = (const float*)d_in[9];
    float* x = (float*)d_out;

    float *ph, *pq, *pk, *pv, *pa, *pf;
    cudaGetSymbolAddress((void**)&ph, g_h);
    cudaGetSymbolAddress((void**)&pq, g_q);
    cudaGetSymbolAddress((void**)&pk, g_k);
    cudaGetSymbolAddress((void**)&pv, g_v);
    cudaGetSymbolAddress((void**)&pa, g_a);
    cudaGetSymbolAddress((void**)&pf, g_f);

    // x = input (residual stream lives in d_out)
    cudaMemcpyAsync(x, x_in, (size_t)MR * DD * sizeof(float),
                    cudaMemcpyDeviceToDevice, 0);

    dim3 gD(DD / 128, MR / 128);     // (8,16) for D-wide GEMMs
    dim3 gF(DFF_ / 128, MR / 128);   // (32,16) for fc1

    for (int i = 0; i < NL_; i++) {
        const float* qwi  = qw    + (size_t)i * DD * DD;
        const float* kwi  = kw    + (size_t)i * DD * DD;
        const float* vwi  = vw    + (size_t)i * DD * DD;
        const float* owi  = ow    + (size_t)i * DD * DD;
        const float* fwi  = fc_w  + (size_t)i * DFF_ * DD;
        const float* f2wi = fc2_w + (size_t)i * DD * DFF_;
        const float* f2bi = fc2_b + (size_t)i * DD;

        // --- attention block ---
        rmsnorm_kernel<<<MR, 256>>>(x, pn_w + (size_t)i * DD, ph);
        gemm_nt<0><<<gD, 256>>>(ph, qwi, pq, nullptr, DD);
        gemm_nt<0><<<gD, 256>>>(ph, kwi, pk, nullptr, DD);
        gemm_nt<0><<<gD, 256>>>(ph, vwi, pv, nullptr, DD);
        linattn_kernel<<<BB * HH, 256>>>(pq, pk, pv, pa);
        gemm_nt<1><<<gD, 256>>>(pa, owi, x, nullptr, DD);   // x += a @ ow^T

        // --- MLP block ---
        rmsnorm_kernel<<<MR, 256>>>(x, ln_w + (size_t)i * DD, ph);
        gemm_nt<2><<<gF, 256>>>(ph, fwi, pf, nullptr, DD);  // f = gelu(h @ fc^T)
        gemm_nt<1><<<gD, 256>>>(pf, f2wi, x, f2bi, DFF_);   // x += f @ fc2^T + b
    }
}

// round 12
// speedup vs baseline: 2.7165x; 2.7165x over previous
#include <cuda_runtime.h>
#include <cuda_bf16.h>
#include <math.h>
#include <stdint.h>

#define BB   2
#define LL   1024
#define DD   1024
#define HH   16
#define DH   64
#define DFF_ 4096
#define NL_  2
#define MR   (BB*LL)   // 2048 rows

typedef __nv_bfloat16 bf16;

// ---------------- scratch (static __device__, no allocation) ----------------
__device__ float g_q[MR*DD];
__device__ float g_k[MR*DD];
__device__ float g_v[MR*DD];

__device__ bf16 g_hhi[MR*DD],  g_hlo[MR*DD];
__device__ bf16 g_ahi[MR*DD],  g_alo[MR*DD];
__device__ bf16 g_fhi[MR*DFF_], g_flo[MR*DFF_];

__device__ bf16 g_wqhi[NL_*DD*DD],  g_wqlo[NL_*DD*DD];
__device__ bf16 g_wkhi[NL_*DD*DD],  g_wklo[NL_*DD*DD];
__device__ bf16 g_wvhi[NL_*DD*DD],  g_wvlo[NL_*DD*DD];
__device__ bf16 g_wohi[NL_*DD*DD],  g_wolo[NL_*DD*DD];
__device__ bf16 g_w1hi[NL_*DFF_*DD], g_w1lo[NL_*DFF_*DD];
__device__ bf16 g_w2hi[NL_*DD*DFF_], g_w2lo[NL_*DD*DFF_];

// ---------------- PTX helpers (sm_80+ baseline features only) ----------------
__device__ __forceinline__ uint32_t smem_u32(const void* p) {
    uint32_t a;
    asm("{ .reg .u64 t; cvta.to.shared.u64 t, %1; cvt.u32.u64 %0, t; }" : "=r"(a) : "l"(p));
    return a;
}
#define CP16(saddr, gaddr) \
    asm volatile("cp.async.cg.shared.global [%0], [%1], 16;" :: "r"(saddr), "l"(gaddr) : "memory")
#define CP_COMMIT() asm volatile("cp.async.commit_group;" ::: "memory")

__device__ __forceinline__ void ldm4(uint32_t* r, uint32_t addr) {
    asm volatile("ldmatrix.sync.aligned.m8n8.x4.shared.b16 {%0,%1,%2,%3}, [%4];"
                 : "=r"(r[0]), "=r"(r[1]), "=r"(r[2]), "=r"(r[3]) : "r"(addr));
}
__device__ __forceinline__ void mma16816(float* d, const uint32_t* a,
                                         uint32_t b0, uint32_t b1) {
    asm volatile("mma.sync.aligned.m16n8k16.row.col.f32.bf16.bf16.f32 "
                 "{%0,%1,%2,%3}, {%4,%5,%6,%7}, {%8,%9}, {%0,%1,%2,%3};"
                 : "+f"(d[0]), "+f"(d[1]), "+f"(d[2]), "+f"(d[3])
                 : "r"(a[0]), "r"(a[1]), "r"(a[2]), "r"(a[3]), "r"(b0), "r"(b1));
}

__device__ __forceinline__ void split_bf(float x, bf16& h, bf16& l) {
    h = __float2bfloat16_rn(x);
    l = __float2bfloat16_rn(x - __bfloat162float(h));
}

// ---------------- weight fp32 -> bf16 hi/lo ----------------
__global__ void cvt_kernel(const float* __restrict__ x, bf16* __restrict__ hi,
                           bf16* __restrict__ lo) {
    int i = blockIdx.x * 256 + threadIdx.x;
    float4 v = ((const float4*)x)[i];
    bf16 h0, h1, h2, h3, l0, l1, l2, l3;
    split_bf(v.x, h0, l0); split_bf(v.y, h1, l1);
    split_bf(v.z, h2, l2); split_bf(v.w, h3, l3);
    __nv_bfloat162* ph = (__nv_bfloat162*)hi;
    __nv_bfloat162* pl = (__nv_bfloat162*)lo;
    ph[i*2]   = __halves2bfloat162(h0, h1);
    ph[i*2+1] = __halves2bfloat162(h2, h3);
    pl[i*2]   = __halves2bfloat162(l0, l1);
    pl[i*2+1] = __halves2bfloat162(l2, l3);
}

// ---------------- rmsnorm -> bf16 hi/lo ----------------
__global__ void rmsnorm_cvt(const float* __restrict__ x, const float* __restrict__ w,
                            bf16* __restrict__ hi, bf16* __restrict__ lo) {
    int row = blockIdx.x;
    int t = threadIdx.x;
    float4 v = ((const float4*)(x + (size_t)row * DD))[t];
    float ss = v.x*v.x + v.y*v.y + v.z*v.z + v.w*v.w;
    #pragma unroll
    for (int o = 16; o; o >>= 1) ss += __shfl_xor_sync(0xFFFFFFFFu, ss, o);
    __shared__ float wsum[8];
    __shared__ float inv_s;
    if ((t & 31) == 0) wsum[t >> 5] = ss;
    __syncthreads();
    if (t == 0) {
        float tot = 0.f;
        #pragma unroll
        for (int i = 0; i < 8; i++) tot += wsum[i];
        inv_s = rsqrtf(tot * (1.0f / DD) + 1e-5f);
    }
    __syncthreads();
    float inv = inv_s;
    float4 wv = ((const float4*)w)[t];
    float r0 = v.x*inv*wv.x, r1 = v.y*inv*wv.y, r2 = v.z*inv*wv.z, r3 = v.w*inv*wv.w;
    bf16 h0,h1,h2,h3,l0,l1,l2,l3;
    split_bf(r0,h0,l0); split_bf(r1,h1,l1); split_bf(r2,h2,l2); split_bf(r3,h3,l3);
    __nv_bfloat162* ph = (__nv_bfloat162*)(hi + (size_t)row * DD);
    __nv_bfloat162* pl = (__nv_bfloat162*)(lo + (size_t)row * DD);
    ph[t*2]   = __halves2bfloat162(h0,h1);
    ph[t*2+1] = __halves2bfloat162(h2,h3);
    pl[t*2]   = __halves2bfloat162(l0,l1);
    pl[t*2+1] = __halves2bfloat162(l2,l3);
}

// ---------------- mma.sync GEMM: C[M,N] = A[M,K] * B[N,K]^T (3-term bf16 split) ----
// 128x128 CTA tile, BK=64, 2-stage cp.async pipeline, 8 warps (4 in M x 2 in N),
// warp tile 32x64, m16n8k16 HMMA, fp32 register accumulators.
// EPI 0: fp32 store; 1: residual add (+bias) fp32; 2: exact GELU -> bf16 hi/lo
#define SMEM_GEMM (1024 + 2*4*16384)   // 132096

template<int EPI>
__global__ void __launch_bounds__(256, 1)
gemm_tc(const bf16* __restrict__ Ahi, const bf16* __restrict__ Alo,
        const bf16* __restrict__ Bhi, const bf16* __restrict__ Blo,
        float* __restrict__ C, const float* __restrict__ bias,
        bf16* __restrict__ Ohi, bf16* __restrict__ Olo, int K, int N) {
    extern __shared__ __align__(1024) char smem[];
    uint32_t sb = smem_u32(smem);
    int t = threadIdx.x;
    int wid = t >> 5, lid = t & 31;
    int bx = blockIdx.x, by = blockIdx.y;

    int wm = (wid & 3) << 5;        // warp M offset within tile (0..96)
    int wn = (wid >> 2) << 6;       // warp N offset within tile (0 or 64)
    int lane15 = lid & 15, khalf = lid >> 4;

    const bf16* mats[4] = {
        Ahi + (size_t)(by << 7) * K, Alo + (size_t)(by << 7) * K,
        Bhi + (size_t)(bx << 7) * K, Blo + (size_t)(bx << 7) * K };

    auto issue = [&](int c) {
        uint32_t sbase = sb + 1024 + (c & 1) * 65536;
        #pragma unroll
        for (int i = 0; i < 16; i++) {
            int u = t + (i << 8);
            int tile = u >> 10, w = u & 1023;
            int row = w >> 3, c16 = w & 7;
            const bf16* g = mats[tile] + (size_t)row * K + (c16 << 3) + ((size_t)c << 6);
            uint32_t so = sbase + tile * 16384 + row * 128 + ((c16 ^ (row & 7)) << 4);
            CP16(so, g);
        }
        CP_COMMIT();
    };

    float acc[2][8][4];
    #pragma unroll
    for (int a = 0; a < 2; a++)
        #pragma unroll
        for (int b = 0; b < 8; b++)
            #pragma unroll
            for (int k = 0; k < 4; k++) acc[a][b][k] = 0.f;

    int nch = K >> 6;
    issue(0);
    if (nch > 1) issue(1);

    for (int c = 0; c < nch; c++) {
        int s = c & 1;
        if (c + 1 < nch) { asm volatile("cp.async.wait_group 1;" ::: "memory"); }
        else             { asm volatile("cp.async.wait_group 0;" ::: "memory"); }
        __syncthreads();

        uint32_t so = sb + 1024 + s * 65536;
        #pragma unroll
        for (int ks = 0; ks < 4; ks++) {
            int c16 = (ks << 1) + khalf;
            uint32_t Ah[2][4], Al[2][4], Bh[4][4], Bl[4][4];
            #pragma unroll
            for (int mf = 0; mf < 2; mf++) {
                int row = wm + (mf << 4) + lane15;
                uint32_t off = row * 128 + ((c16 ^ (row & 7)) << 4);
                ldm4(Ah[mf], so + off);
                ldm4(Al[mf], so + 16384 + off);
            }
            #pragma unroll
            for (int nf = 0; nf < 4; nf++) {
                int row = wn + (nf << 4) + lane15;
                uint32_t off = row * 128 + ((c16 ^ (row & 7)) << 4);
                ldm4(Bh[nf], so + 32768 + off);
                ldm4(Bl[nf], so + 49152 + off);
            }
            #pragma unroll
            for (int mf = 0; mf < 2; mf++)
                #pragma unroll
                for (int nf = 0; nf < 4; nf++)
                    #pragma unroll
                    for (int hf = 0; hf < 2; hf++) {
                        float* d = acc[mf][(nf << 1) + hf];
                        mma16816(d, Ah[mf], Bh[nf][hf], Bh[nf][hf + 2]);
                        mma16816(d, Ah[mf], Bl[nf][hf], Bl[nf][hf + 2]);
                        mma16816(d, Al[mf], Bh[nf][hf], Bh[nf][hf + 2]);
                    }
        }
        __syncthreads();
        if (c + 2 < nch) issue(c + 2);
    }

    // epilogue: lane l owns (row tr, cols tc..tc+1) and (row tr+8, same cols)
    int tr = lid >> 2, tc = (lid & 3) << 1;
    #pragma unroll
    for (int mf = 0; mf < 2; mf++) {
        int r0 = (by << 7) + wm + (mf << 4) + tr;
        #pragma unroll
        for (int nf = 0; nf < 8; nf++) {
            int col = (bx << 7) + wn + (nf << 3) + tc;
            float* d = acc[mf][nf];
            if (EPI == 2) {
                #pragma unroll
                for (int hf = 0; hf < 2; hf++) {
                    int r = r0 + hf * 8;
                    float v0 = d[hf * 2], v1 = d[hf * 2 + 1];
                    v0 = 0.5f * v0 * (1.0f + erff(v0 * 0.7071067811865476f));
                    v1 = 0.5f * v1 * (1.0f + erff(v1 * 0.7071067811865476f));
                    bf16 h0, h1, l0, l1;
                    split_bf(v0, h0, l0); split_bf(v1, h1, l1);
                    *(__nv_bfloat162*)(Ohi + (size_t)r * N + col) = __halves2bfloat162(h0, h1);
                    *(__nv_bfloat162*)(Olo + (size_t)r * N + col) = __halves2bfloat162(l0, l1);
                }
            } else {
                #pragma unroll
                for (int hf = 0; hf < 2; hf++) {
                    int r = r0 + hf * 8;
                    float2* cp = (float2*)(C + (size_t)r * N + col);
                    float2 v; v.x = d[hf * 2]; v.y = d[hf * 2 + 1];
                    if (EPI == 1) {
                        float2 cv = *cp;
                        v.x += cv.x; v.y += cv.y;
                        if (bias) {
                            float2 bv = *(const float2*)(bias + col);
                            v.x += bv.x; v.y += bv.y;
                        }
                    }
                    *cp = v;
                }
            }
        }
    }
}

// ---------------- causal linear attention scan (fp32) -> bf16 hi/lo output ----
// block per (b,h); 256 thr: e = t>>2, dg = t&3; 2 timesteps per barrier.
__global__ void __launch_bounds__(256) linattn_kernel(
        const float* __restrict__ Q, const float* __restrict__ K,
        const float* __restrict__ V, bf16* __restrict__ Ahi, bf16* __restrict__ Alo) {
    int b = blockIdx.x >> 4;
    int h = blockIdx.x & 15;
    int t = threadIdx.x;
    int e = t >> 2, dg = t & 3;

    __shared__ float buf[2][2][192];   // [stage][sub][ K:0-63 | V:64-127 | Q:128-191 ]

    float s[16];
    #pragma unroll
    for (int j = 0; j < 16; j++) s[j] = 0.f;

    size_t base = (size_t)b * LL * DD + (size_t)h * DH;
    const float* srcp = nullptr;
    if (t < 192) {
        int arr = t >> 6, idx = t & 63;
        const float* m = (arr == 0) ? K : (arr == 1) ? V : Q;
        srcp = m + base + idx;
    }
    float r0 = 0.f, r1 = 0.f;
    if (t < 192) { r0 = srcp[0]; r1 = srcp[DD]; }

    for (int it = 0; it < LL / 2; it++) {
        int st = it & 1;
        if (t < 192) { buf[st][0][t] = r0; buf[st][1][t] = r1; }
        __syncthreads();
        if (t < 192 && it + 1 < LL / 2) {
            size_t o = (size_t)(2 * it + 2) * DD;
            r0 = srcp[o]; r1 = srcp[o + DD];
        }
        #pragma unroll
        for (int sub = 0; sub < 2; sub++) {
            const float* bp = buf[st][sub];
            const float4* kb = (const float4*)bp;
            const float4* qb = (const float4*)(bp + 128);
            float ve = bp[64 + e];
            float p = 0.f;
            #pragma unroll
            for (int m = 0; m < 4; m++) {
                float4 k4 = kb[dg * 4 + m];
                float4 q4 = qb[dg * 4 + m];
                s[m*4+0] = fmaf(k4.x, ve, s[m*4+0]); p = fmaf(q4.x, s[m*4+0], p);
                s[m*4+1] = fmaf(k4.y, ve, s[m*4+1]); p = fmaf(q4.y, s[m*4+1], p);
                s[m*4+2] = fmaf(k4.z, ve, s[m*4+2]); p = fmaf(q4.z, s[m*4+2], p);
                s[m*4+3] = fmaf(k4.w, ve, s[m*4+3]); p = fmaf(q4.w, s[m*4+3], p);
            }
            p += __shfl_xor_sync(0xFFFFFFFFu, p, 1);
            p += __shfl_xor_sync(0xFFFFFFFFu, p, 2);
            if (dg == 0) {
                size_t off = base + (size_t)(2 * it + sub) * DD + e;
                bf16 hv, lv; split_bf(p, hv, lv);
                Ahi[off] = hv; Alo[off] = lv;
            }
        }
        __syncthreads();
    }
}

// ---------------- host launcher ----------------
extern "C" void kernel_launch(void* const* d_in, const int* in_sizes, int n_in,
                              void* d_out, int out_size) {
    const float* x_in  = (const float*)d_in[0];
    const float* qw    = (const float*)d_in[1];
    const float* kw    = (const float*)d_in[2];
    const float* vw    = (const float*)d_in[3];
    const float* ow    = (const float*)d_in[4];
    const float* pn_w  = (const float*)d_in[5];
    const float* ln_w  = (const float*)d_in[6];
    const float* fc_w  = (const float*)d_in[7];
    const float* fc2_w = (const float*)d_in[8];
    const float* fc2_b = (const float*)d_in[9];
    float* x = (float*)d_out;

    float *pq, *pk, *pv;
    bf16 *hhi, *hlo, *ahi, *alo, *fhi, *flo;
    bf16 *wqh, *wql, *wkh, *wkl, *wvh, *wvl, *woh, *wol, *w1h, *w1l, *w2h, *w2l;
    cudaGetSymbolAddress((void**)&pq,  g_q);
    cudaGetSymbolAddress((void**)&pk,  g_k);
    cudaGetSymbolAddress((void**)&pv,  g_v);
    cudaGetSymbolAddress((void**)&hhi, g_hhi); cudaGetSymbolAddress((void**)&hlo, g_hlo);
    cudaGetSymbolAddress((void**)&ahi, g_ahi); cudaGetSymbolAddress((void**)&alo, g_alo);
    cudaGetSymbolAddress((void**)&fhi, g_fhi); cudaGetSymbolAddress((void**)&flo, g_flo);
    cudaGetSymbolAddress((void**)&wqh, g_wqhi); cudaGetSymbolAddress((void**)&wql, g_wqlo);
    cudaGetSymbolAddress((void**)&wkh, g_wkhi); cudaGetSymbolAddress((void**)&wkl, g_wklo);
    cudaGetSymbolAddress((void**)&wvh, g_wvhi); cudaGetSymbolAddress((void**)&wvl, g_wvlo);
    cudaGetSymbolAddress((void**)&woh, g_wohi); cudaGetSymbolAddress((void**)&wol, g_wolo);
    cudaGetSymbolAddress((void**)&w1h, g_w1hi); cudaGetSymbolAddress((void**)&w1l, g_w1lo);
    cudaGetSymbolAddress((void**)&w2h, g_w2hi); cudaGetSymbolAddress((void**)&w2l, g_w2lo);

    cudaFuncSetAttribute(gemm_tc<0>, cudaFuncAttributeMaxDynamicSharedMemorySize, SMEM_GEMM);
    cudaFuncSetAttribute(gemm_tc<1>, cudaFuncAttributeMaxDynamicSharedMemorySize, SMEM_GEMM);
    cudaFuncSetAttribute(gemm_tc<2>, cudaFuncAttributeMaxDynamicSharedMemorySize, SMEM_GEMM);

    cudaMemcpyAsync(x, x_in, (size_t)MR * DD * sizeof(float),
                    cudaMemcpyDeviceToDevice, 0);

    // weight conversions (per replay; deterministic)
    const int nDD  = NL_ * DD * DD;      // 2M
    const int nF   = NL_ * DFF_ * DD;    // 8M
    cvt_kernel<<<nDD / 1024, 256>>>(qw,    wqh, wql);
    cvt_kernel<<<nDD / 1024, 256>>>(kw,    wkh, wkl);
    cvt_kernel<<<nDD / 1024, 256>>>(vw,    wvh, wvl);
    cvt_kernel<<<nDD / 1024, 256>>>(ow,    woh, wol);
    cvt_kernel<<<nF  / 1024, 256>>>(fc_w,  w1h, w1l);
    cvt_kernel<<<nF  / 1024, 256>>>(fc2_w, w2h, w2l);

    dim3 gD(DD / 128, MR / 128);     // (8,16)
    dim3 gF(DFF_ / 128, MR / 128);   // (32,16)

    for (int i = 0; i < NL_; i++) {
        size_t oD = (size_t)i * DD * DD;
        size_t oF = (size_t)i * DFF_ * DD;

        // --- attention block ---
        rmsnorm_cvt<<<MR, 256>>>(x, pn_w + (size_t)i * DD, hhi, hlo);
        gemm_tc<0><<<gD, 256, SMEM_GEMM>>>(hhi, hlo, wqh + oD, wql + oD,
                                           pq, nullptr, nullptr, nullptr, DD, DD);
        gemm_tc<0><<<gD, 256, SMEM_GEMM>>>(hhi, hlo, wkh + oD, wkl + oD,
                                           pk, nullptr, nullptr, nullptr, DD, DD);
        gemm_tc<0><<<gD, 256, SMEM_GEMM>>>(hhi, hlo, wvh + oD, wvl + oD,
                                           pv, nullptr, nullptr, nullptr, DD, DD);
        linattn_kernel<<<BB * HH, 256>>>(pq, pk, pv, ahi, alo);
        gemm_tc<1><<<gD, 256, SMEM_GEMM>>>(ahi, alo, woh + oD, wol + oD,
                                           x, nullptr, nullptr, nullptr, DD, DD);

        // --- MLP block ---
        rmsnorm_cvt<<<MR, 256>>>(x, ln_w + (size_t)i * DD, hhi, hlo);
        gemm_tc<2><<<gF, 256, SMEM_GEMM>>>(hhi, hlo, w1h + oF, w1l + oF,
                                           nullptr, nullptr, fhi, flo, DD, DFF_);
        gemm_tc<1><<<gD, 256, SMEM_GEMM>>>(fhi, flo, w2h + oF, w2l + oF,
                                           x, fc2_b + (size_t)i * DD, nullptr, nullptr,
                                           DFF_, DD);
    }
}